// round 6
// baseline (speedup 1.0000x reference)
#include <cuda_runtime.h>
#include <cuda_bf16.h>
#include <cstdint>

#define B_  8
#define C_  64
#define H_  128
#define W_  128
#define OC_ 128
#define HP_ 130
#define WP_ 130

#define ROWB 16640               // one padded row slab: 130 px * 64 ch * 2 B
#define SW_STAGE 16384
#define SE_OFF   (3 * SW_STAGE)              // 49152
#define RZ_OFF   (SE_OFF + 4 * ROWB)         // 115712
#define CONV_SMEM (RZ_OFF + 1024)            // 116736

// E transposed: [b][hp][wp][c] bf16, border ring = 1.0 (= exp(0))
__device__ __nv_bfloat16 g_Egt[(size_t)B_ * HP_ * WP_ * C_];  // ~17.3 MB
__device__ float         g_Cs[(size_t)B_ * HP_ * WP_];        // channel sums, ring = 64
__device__ __nv_bfloat16 g_Wr[9 * OC_ * C_];                  // [tap][oc][c]

// ---------------------------------------------------------------------------
__device__ __forceinline__ uint32_t smem_u32(const void* p) {
    uint32_t a;
    asm("{ .reg .u64 t; cvta.to.shared.u64 t, %1; cvt.u32.u64 %0, t; }" : "=r"(a) : "l"(p));
    return a;
}
#define CP_ASYNC16(sa, ga) \
    asm volatile("cp.async.cg.shared.global [%0], [%1], 16;" :: "r"(sa), "l"(ga) : "memory")
#define CP_COMMIT() asm volatile("cp.async.commit_group;" ::: "memory")
#define CP_WAIT(n)  asm volatile("cp.async.wait_group %0;" :: "n"(n) : "memory")
#define LDSM_X4(r0, r1, r2, r3, addr) \
    asm volatile("ldmatrix.sync.aligned.m8n8.x4.shared.b16 {%0,%1,%2,%3}, [%4];" \
        : "=r"(r0), "=r"(r1), "=r"(r2), "=r"(r3) : "r"(addr))

__device__ __forceinline__ void mma16816(float* c, const uint32_t* a,
                                         uint32_t b0, uint32_t b1) {
    asm volatile(
        "mma.sync.aligned.m16n8k16.row.col.f32.bf16.bf16.f32 "
        "{%0,%1,%2,%3}, {%4,%5,%6,%7}, {%8,%9}, {%0,%1,%2,%3};"
        : "+f"(c[0]), "+f"(c[1]), "+f"(c[2]), "+f"(c[3])
        : "r"(a[0]), "r"(a[1]), "r"(a[2]), "r"(a[3]), "r"(b0), "r"(b1));
}

// ---------------------------------------------------------------------------
// Fused pre-kernel: blocks [0,2048): exp+transpose+chansum
//                   blocks [2048,..): weight rearrange + border ring
// ---------------------------------------------------------------------------
#define EXP_BLOCKS 2048
#define PREP_TOTAL (9 * OC_ * C_ + B_ * 516)
#define PRE_GRID   (EXP_BLOCKS + (PREP_TOTAL + 255) / 256)

__global__ __launch_bounds__(256) void pre_kernel(const float* __restrict__ x,
                                                  const float* __restrict__ mem) {
    const int bid = blockIdx.x;
    const int tid = threadIdx.x;

    if (bid >= EXP_BLOCKS) {
        int idx = (bid - EXP_BLOCKS) * 256 + tid;
        if (idx < 9 * OC_ * C_) {
            int c   = idx & 63;
            int oc  = (idx >> 6) & 127;
            int tap = idx >> 13;
            g_Wr[idx] = __float2bfloat16(mem[(c * 9 + tap) * OC_ + oc]);
            return;
        }
        idx -= 9 * OC_ * C_;
        if (idx >= B_ * 516) return;
        int b = idx / 516, p = idx % 516;
        int hp, wp;
        if (p < 260) { hp = (p < 130) ? 0 : (HP_ - 1); wp = p % 130; }
        else { int q = p - 260; hp = 1 + (q & 127); wp = (q < 128) ? 0 : (WP_ - 1); }
        size_t pix = ((size_t)b * HP_ + hp) * WP_ + wp;
        uint4 ones = make_uint4(0x3F803F80u, 0x3F803F80u, 0x3F803F80u, 0x3F803F80u);
        uint4* dst = reinterpret_cast<uint4*>(g_Egt + pix * C_);
#pragma unroll
        for (int i = 0; i < 8; i++) dst[i] = ones;
        g_Cs[pix] = 64.0f;
        return;
    }

    __shared__ float sm[C_][65];
    const int w0 = (bid & 1) * 64;
    const int h  = (bid >> 1) & 127;
    const int b  = bid >> 8;
    const int px = tid & 63, cq = tid >> 6;

    const float* xb = x + (((size_t)b * C_) * H_ + h) * W_ + w0 + px;
#pragma unroll
    for (int it = 0; it < 16; it++) {
        int c = it * 4 + cq;
        sm[c][px] = __expf(xb[(size_t)c * H_ * W_]);
    }
    __syncthreads();

    if (tid < 64) {
        float s = 0.f;
#pragma unroll
        for (int c = 0; c < C_; c++) s += sm[c][tid];
        g_Cs[((size_t)b * HP_ + h + 1) * WP_ + (w0 + tid + 1)] = s;
    }

    const int seg = tid & 7, r0 = tid >> 3;
#pragma unroll
    for (int pass = 0; pass < 2; pass++) {
        int r = pass * 32 + r0;
        uint32_t pk[4];
#pragma unroll
        for (int j = 0; j < 4; j++) {
            __nv_bfloat162 v = __floats2bfloat162_rn(sm[seg * 8 + 2 * j][r],
                                                     sm[seg * 8 + 2 * j + 1][r]);
            pk[j] = *reinterpret_cast<uint32_t*>(&v);
        }
        size_t pix = ((size_t)b * HP_ + h + 1) * WP_ + (w0 + r + 1);
        reinterpret_cast<uint4*>(g_Egt + pix * C_)[seg] = make_uint4(pk[0], pk[1], pk[2], pk[3]);
    }
}

// ---------------------------------------------------------------------------
// Conv: per CTA: 2 output rows. D[128 oc, 256 px], 512 thr / 16 warps (2M x 8N).
// E rows h0..h0+3 resident; W 3-stage cp.async; 9 taps, 1 sync per tap.
// ---------------------------------------------------------------------------
__global__ void __launch_bounds__(512, 1) conv_mma_kernel(float* __restrict__ out) {
    extern __shared__ __align__(128) char smem[];
    const uint32_t sbase = smem_u32(smem);
    const int tid  = threadIdx.x;
    const int wid  = tid >> 5, lane = tid & 31;
    const int h0 = blockIdx.x * 2, b = blockIdx.y;
    const int wm = wid & 1;                 // M half
    const int wq = wid >> 1;                // 0..7
    const int row_sel = wq >> 2;            // output row within CTA
    const int wn4 = wq & 3;                 // px quarter (32 px)

    const char* EgB = reinterpret_cast<const char*>(g_Egt) + (size_t)b * HP_ * WP_ * C_ * 2;

    auto issueW = [&](int t, int s) {
        const uint4* srcA = reinterpret_cast<const uint4*>(g_Wr + t * OC_ * C_);
        const uint32_t dA = sbase + s * SW_STAGE;
#pragma unroll
        for (int p = 0; p < 2; p++) {
            int c = p * 512 + tid;
            int off  = c * 16;
            int soff = off ^ ((off >> 3) & 0x70);
            CP_ASYNC16(dA + soff, srcA + c);
        }
    };

    // ---- prologue: E rows h0..h0+3 (contiguous 66560B) + W0; then W1 ----
    {
        const char* srcE = EgB + (size_t)h0 * ROWB;
        for (int i = tid; i < 4160; i += 512) {
            int slab = i / 1040;
            int r    = i - slab * 1040;
            int off  = r * 16;
            int soff = off ^ ((off >> 3) & 0x70);
            CP_ASYNC16(sbase + SE_OFF + slab * ROWB + soff, srcE + (size_t)i * 16);
        }
    }
    issueW(0, 0); CP_COMMIT();   // g0 = E + W0
    issueW(1, 1); CP_COMMIT();   // g1 = W1

    // ---- softmax denominator early (overlaps cp.async) ----
    float* rz = reinterpret_cast<float*>(smem + RZ_OFF);
    if (tid < 256) {
        const int rs = tid >> 7, w = tid & 127;
        const float* Cb = g_Cs + ((size_t)b * HP_ + h0 + rs) * WP_ + w;
        float s = 0.f;
#pragma unroll
        for (int i = 0; i < 3; i++)
#pragma unroll
            for (int j = 0; j < 3; j++) s += Cb[i * WP_ + j];
        rz[tid] = 1.0f / s;
    }

    float acc[4][4][4];
#pragma unroll
    for (int i = 0; i < 4; i++)
#pragma unroll
        for (int j = 0; j < 4; j++)
#pragma unroll
            for (int k = 0; k < 4; k++) acc[i][j][k] = 0.f;

    int aRow[4], aSw[4];
#pragma unroll
    for (int mi = 0; mi < 4; mi++) {
        int row = wm * 64 + mi * 16 + (lane & 15);
        aRow[mi] = row * 128;
        aSw[mi]  = (row & 7) * 16;
    }
    const int aCol = (lane >> 4) << 4;
    int bRowBase[2];
#pragma unroll
    for (int nb = 0; nb < 2; nb++)
        bRowBase[nb] = wn4 * 32 + nb * 16 + ((lane >> 4) << 3) + (lane & 7);
    const int bCol = ((lane >> 3) & 1) << 4;

#pragma unroll 1
    for (int t = 0; t < 9; t++) {
        if (t < 8) CP_WAIT(1); else CP_WAIT(0);
        __syncthreads();
        if (t < 7) { issueW(t + 2, (t + 2) % 3); CP_COMMIT(); }

        const int kh = t / 3, kw = t - 3 * kh;
        const uint32_t sA = sbase + (t % 3) * SW_STAGE;
        const uint32_t sE = sbase + SE_OFF + (kh + row_sel) * ROWB;

#pragma unroll
        for (int ks = 0; ks < 4; ks++) {
            uint32_t a[4][4];
#pragma unroll
            for (int mi = 0; mi < 4; mi++) {
                uint32_t addr = sA + aRow[mi] + ((ks * 32 + aCol) ^ aSw[mi]);
                LDSM_X4(a[mi][0], a[mi][1], a[mi][2], a[mi][3], addr);
            }
            uint32_t bf[2][4];
#pragma unroll
            for (int nb = 0; nb < 2; nb++) {
                int row = bRowBase[nb] + kw;
                uint32_t addr = sE + row * 128 + ((ks * 32 + bCol) ^ ((row & 7) * 16));
                LDSM_X4(bf[nb][0], bf[nb][1], bf[nb][2], bf[nb][3], addr);
            }
#pragma unroll
            for (int mi = 0; mi < 4; mi++)
#pragma unroll
                for (int ni = 0; ni < 4; ni++) {
                    uint32_t b0 = bf[ni >> 1][(ni & 1) * 2];
                    uint32_t b1 = bf[ni >> 1][(ni & 1) * 2 + 1];
                    mma16816(acc[mi][ni], a[mi], b0, b1);
                }
        }
    }
    __syncthreads();

    // ---- epilogue: scale + store ----
    const int h = h0 + row_sel;
#pragma unroll
    for (int mi = 0; mi < 4; mi++)
#pragma unroll
        for (int ni = 0; ni < 4; ni++) {
            int oc = wm * 64 + mi * 16 + (lane >> 2);
            int w  = wn4 * 32 + ni * 8 + (lane & 3) * 2;
            float z0 = rz[row_sel * 128 + w], z1 = rz[row_sel * 128 + w + 1];
            float* p0 = out + (((size_t)b * OC_ + oc) * H_ + h) * W_ + w;
            float2 v0 = make_float2(acc[mi][ni][0] * z0, acc[mi][ni][1] * z1);
            float2 v1 = make_float2(acc[mi][ni][2] * z0, acc[mi][ni][3] * z1);
            *reinterpret_cast<float2*>(p0) = v0;
            *reinterpret_cast<float2*>(p0 + (size_t)8 * H_ * W_) = v1;
        }
}

// ---------------------------------------------------------------------------
extern "C" void kernel_launch(void* const* d_in, const int* in_sizes, int n_in,
                              void* d_out, int out_size) {
    const float* x   = (const float*)d_in[0];   // [8,64,128,128]
    const float* mem = (const float*)d_in[1];   // [576,128]
    float* out = (float*)d_out;                 // [8,128,128,128]

    cudaFuncSetAttribute(conv_mma_kernel,
                         cudaFuncAttributeMaxDynamicSharedMemorySize, CONV_SMEM);

    pre_kernel<<<PRE_GRID, 256>>>(x, mem);
    conv_mma_kernel<<<dim3(H_ / 2, B_), 512, CONV_SMEM>>>(out);
}

// round 7
// speedup vs baseline: 1.0353x; 1.0353x over previous
#include <cuda_runtime.h>
#include <cuda_bf16.h>
#include <cstdint>

#define B_  8
#define C_  64
#define H_  128
#define W_  128
#define OC_ 128
#define HP_ 130
#define WP_ 130

#define ROWB 16640               // one padded row slab: 130 px * 64 ch * 2 B
#define TAPB 16384               // one tap of W
#define STAGE2 32768             // 2 taps per stage
#define SE_OFF   (2 * STAGE2)                // 65536
#define RZ_OFF   (SE_OFF + 3 * ROWB)         // 115456
#define CONV_SMEM (RZ_OFF + 512)             // 115968  (<=116736 for 2 CTAs/SM)

// E transposed: [b][hp][wp][c] bf16, border ring = 1.0 (= exp(0))
__device__ __nv_bfloat16 g_Egt[(size_t)B_ * HP_ * WP_ * C_];  // ~17.3 MB
__device__ float         g_Cs[(size_t)B_ * HP_ * WP_];        // channel sums, ring = 64
__device__ __nv_bfloat16 g_Wr[9 * OC_ * C_];                  // [tap][oc][c]

// ---------------------------------------------------------------------------
__device__ __forceinline__ uint32_t smem_u32(const void* p) {
    uint32_t a;
    asm("{ .reg .u64 t; cvta.to.shared.u64 t, %1; cvt.u32.u64 %0, t; }" : "=r"(a) : "l"(p));
    return a;
}
#define CP_ASYNC16(sa, ga) \
    asm volatile("cp.async.cg.shared.global [%0], [%1], 16;" :: "r"(sa), "l"(ga) : "memory")
#define CP_COMMIT() asm volatile("cp.async.commit_group;" ::: "memory")
#define CP_WAIT(n)  asm volatile("cp.async.wait_group %0;" :: "n"(n) : "memory")
#define LDSM_X4(r0, r1, r2, r3, addr) \
    asm volatile("ldmatrix.sync.aligned.m8n8.x4.shared.b16 {%0,%1,%2,%3}, [%4];" \
        : "=r"(r0), "=r"(r1), "=r"(r2), "=r"(r3) : "r"(addr))

__device__ __forceinline__ void mma16816(float* c, const uint32_t* a,
                                         uint32_t b0, uint32_t b1) {
    asm volatile(
        "mma.sync.aligned.m16n8k16.row.col.f32.bf16.bf16.f32 "
        "{%0,%1,%2,%3}, {%4,%5,%6,%7}, {%8,%9}, {%0,%1,%2,%3};"
        : "+f"(c[0]), "+f"(c[1]), "+f"(c[2]), "+f"(c[3])
        : "r"(a[0]), "r"(a[1]), "r"(a[2]), "r"(a[3]), "r"(b0), "r"(b1));
}

// ---------------------------------------------------------------------------
// Fused pre-kernel: blocks [0,2048): exp+transpose+chansum
//                   blocks [2048,..): weight rearrange + border ring
// ---------------------------------------------------------------------------
#define EXP_BLOCKS 2048
#define PREP_TOTAL (9 * OC_ * C_ + B_ * 516)
#define PRE_GRID   (EXP_BLOCKS + (PREP_TOTAL + 255) / 256)

__global__ __launch_bounds__(256) void pre_kernel(const float* __restrict__ x,
                                                  const float* __restrict__ mem) {
    const int bid = blockIdx.x;
    const int tid = threadIdx.x;

    if (bid >= EXP_BLOCKS) {
        int idx = (bid - EXP_BLOCKS) * 256 + tid;
        if (idx < 9 * OC_ * C_) {
            int c   = idx & 63;
            int oc  = (idx >> 6) & 127;
            int tap = idx >> 13;
            g_Wr[idx] = __float2bfloat16(mem[(c * 9 + tap) * OC_ + oc]);
            return;
        }
        idx -= 9 * OC_ * C_;
        if (idx >= B_ * 516) return;
        int b = idx / 516, p = idx % 516;
        int hp, wp;
        if (p < 260) { hp = (p < 130) ? 0 : (HP_ - 1); wp = p % 130; }
        else { int q = p - 260; hp = 1 + (q & 127); wp = (q < 128) ? 0 : (WP_ - 1); }
        size_t pix = ((size_t)b * HP_ + hp) * WP_ + wp;
        uint4 ones = make_uint4(0x3F803F80u, 0x3F803F80u, 0x3F803F80u, 0x3F803F80u);
        uint4* dst = reinterpret_cast<uint4*>(g_Egt + pix * C_);
#pragma unroll
        for (int i = 0; i < 8; i++) dst[i] = ones;
        g_Cs[pix] = 64.0f;
        return;
    }

    __shared__ float sm[C_][65];
    const int w0 = (bid & 1) * 64;
    const int h  = (bid >> 1) & 127;
    const int b  = bid >> 8;
    const int px = tid & 63, cq = tid >> 6;

    const float* xb = x + (((size_t)b * C_) * H_ + h) * W_ + w0 + px;
#pragma unroll
    for (int it = 0; it < 16; it++) {
        int c = it * 4 + cq;
        sm[c][px] = __expf(xb[(size_t)c * H_ * W_]);
    }
    __syncthreads();

    if (tid < 64) {
        float s = 0.f;
#pragma unroll
        for (int c = 0; c < C_; c++) s += sm[c][tid];
        g_Cs[((size_t)b * HP_ + h + 1) * WP_ + (w0 + tid + 1)] = s;
    }

    const int seg = tid & 7, r0 = tid >> 3;
#pragma unroll
    for (int pass = 0; pass < 2; pass++) {
        int r = pass * 32 + r0;
        uint32_t pk[4];
#pragma unroll
        for (int j = 0; j < 4; j++) {
            __nv_bfloat162 v = __floats2bfloat162_rn(sm[seg * 8 + 2 * j][r],
                                                     sm[seg * 8 + 2 * j + 1][r]);
            pk[j] = *reinterpret_cast<uint32_t*>(&v);
        }
        size_t pix = ((size_t)b * HP_ + h + 1) * WP_ + (w0 + r + 1);
        reinterpret_cast<uint4*>(g_Egt + pix * C_)[seg] = make_uint4(pk[0], pk[1], pk[2], pk[3]);
    }
}

// ---------------------------------------------------------------------------
// Conv: per (b,h): D[128 oc, 128 px] = sum_{9 taps} Wtap[128,64] @ Etap[128,64]^T
// E rows h..h+2 resident; W double-buffered 2-tap stages -> 5 barriers/CTA.
// 8 warps (2M x 4N), 2 CTAs/SM.
// ---------------------------------------------------------------------------
__global__ void __launch_bounds__(256, 2) conv_mma_kernel(float* __restrict__ out) {
    extern __shared__ __align__(128) char smem[];
    const uint32_t sbase = smem_u32(smem);
    const int tid  = threadIdx.x;
    const int wid  = tid >> 5, lane = tid & 31;
    const int h = blockIdx.x, b = blockIdx.y;
    const int wm = wid & 1, wn = wid >> 1;    // 2 x 4 warp grid

    const char* EgB = reinterpret_cast<const char*>(g_Egt) + (size_t)b * HP_ * WP_ * C_ * 2;

    auto issueW = [&](int t, uint32_t dst) {   // one 16KB tap
        const uint4* srcA = reinterpret_cast<const uint4*>(g_Wr + t * OC_ * C_);
#pragma unroll
        for (int p = 0; p < 4; p++) {
            int c = p * 256 + tid;
            int off  = c * 16;
            int soff = off ^ ((off >> 3) & 0x70);
            CP_ASYNC16(dst + soff, srcA + c);
        }
    };

    // ---- prologue: E rows h..h+2 (contiguous 49920B) + stage0 = taps {0,1} ----
    {
        const char* srcE = EgB + (size_t)h * ROWB;
        for (int i = tid; i < 3120; i += 256) {
            int slab = i / 1040;
            int r    = i - slab * 1040;
            int off  = r * 16;
            int soff = off ^ ((off >> 3) & 0x70);
            CP_ASYNC16(sbase + SE_OFF + slab * ROWB + soff, srcE + (size_t)i * 16);
        }
    }
    issueW(0, sbase);
    issueW(1, sbase + TAPB);
    CP_COMMIT();

    // ---- softmax denominator early (overlaps cp.async) ----
    float* rz = reinterpret_cast<float*>(smem + RZ_OFF);
    if (tid < 128) {
        const float* Cb = g_Cs + ((size_t)b * HP_ + h) * WP_ + tid;
        float s = 0.f;
#pragma unroll
        for (int i = 0; i < 3; i++)
#pragma unroll
            for (int j = 0; j < 3; j++) s += Cb[i * WP_ + j];
        rz[tid] = 1.0f / s;
    }

    float acc[4][4][4];
#pragma unroll
    for (int i = 0; i < 4; i++)
#pragma unroll
        for (int j = 0; j < 4; j++)
#pragma unroll
            for (int k = 0; k < 4; k++) acc[i][j][k] = 0.f;

    int aRow[4], aSw[4];
#pragma unroll
    for (int mi = 0; mi < 4; mi++) {
        int row = wm * 64 + mi * 16 + (lane & 15);
        aRow[mi] = row * 128;
        aSw[mi]  = (row & 7) * 16;
    }
    const int aCol = (lane >> 4) << 4;
    int bRowBase[2];
#pragma unroll
    for (int nb = 0; nb < 2; nb++)
        bRowBase[nb] = wn * 32 + nb * 16 + ((lane >> 4) << 3) + (lane & 7);
    const int bCol = ((lane >> 3) & 1) << 4;

#pragma unroll 1
    for (int it = 0; it < 5; it++) {
        CP_WAIT(0);
        __syncthreads();
        // prefetch next 2-tap pair into the other stage (safe: read at it-1, synced)
        {
            int tn = 2 * it + 2;
            if (tn < 9) {
                uint32_t dst = sbase + ((it + 1) & 1) * STAGE2;
                issueW(tn, dst);
                if (tn + 1 < 9) issueW(tn + 1, dst + TAPB);
                CP_COMMIT();
            }
        }

        const uint32_t stg = sbase + (it & 1) * STAGE2;
        const int tcount = (it < 4) ? 2 : 1;
#pragma unroll
        for (int u = 0; u < 2; u++) {
            if (u >= tcount) break;
            const int t  = 2 * it + u;
            const int kh = t / 3, kw = t - 3 * kh;
            const uint32_t sA = stg + u * TAPB;
            const uint32_t sE = sbase + SE_OFF + kh * ROWB;

#pragma unroll
            for (int ks = 0; ks < 4; ks++) {
                uint32_t a[4][4];
#pragma unroll
                for (int mi = 0; mi < 4; mi++) {
                    uint32_t addr = sA + aRow[mi] + ((ks * 32 + aCol) ^ aSw[mi]);
                    LDSM_X4(a[mi][0], a[mi][1], a[mi][2], a[mi][3], addr);
                }
                uint32_t bf[2][4];
#pragma unroll
                for (int nb = 0; nb < 2; nb++) {
                    int row = bRowBase[nb] + kw;
                    uint32_t addr = sE + row * 128 + ((ks * 32 + bCol) ^ ((row & 7) * 16));
                    LDSM_X4(bf[nb][0], bf[nb][1], bf[nb][2], bf[nb][3], addr);
                }
#pragma unroll
                for (int mi = 0; mi < 4; mi++)
#pragma unroll
                    for (int ni = 0; ni < 4; ni++) {
                        uint32_t b0 = bf[ni >> 1][(ni & 1) * 2];
                        uint32_t b1 = bf[ni >> 1][(ni & 1) * 2 + 1];
                        mma16816(acc[mi][ni], a[mi], b0, b1);
                    }
            }
        }
    }
    __syncthreads();

    // ---- epilogue: scale + store ----
#pragma unroll
    for (int mi = 0; mi < 4; mi++)
#pragma unroll
        for (int ni = 0; ni < 4; ni++) {
            int oc = wm * 64 + mi * 16 + (lane >> 2);
            int w  = wn * 32 + ni * 8 + (lane & 3) * 2;
            float z0 = rz[w], z1 = rz[w + 1];
            float* p0 = out + (((size_t)b * OC_ + oc) * H_ + h) * W_ + w;
            float2 v0 = make_float2(acc[mi][ni][0] * z0, acc[mi][ni][1] * z1);
            float2 v1 = make_float2(acc[mi][ni][2] * z0, acc[mi][ni][3] * z1);
            *reinterpret_cast<float2*>(p0) = v0;
            *reinterpret_cast<float2*>(p0 + (size_t)8 * H_ * W_) = v1;
        }
}

// ---------------------------------------------------------------------------
extern "C" void kernel_launch(void* const* d_in, const int* in_sizes, int n_in,
                              void* d_out, int out_size) {
    const float* x   = (const float*)d_in[0];   // [8,64,128,128]
    const float* mem = (const float*)d_in[1];   // [576,128]
    float* out = (float*)d_out;                 // [8,128,128,128]

    cudaFuncSetAttribute(conv_mma_kernel,
                         cudaFuncAttributeMaxDynamicSharedMemorySize, CONV_SMEM);

    pre_kernel<<<PRE_GRID, 256>>>(x, mem);
    conv_mma_kernel<<<dim3(H_, B_), 256, CONV_SMEM>>>(out);
}

// round 8
// speedup vs baseline: 1.1843x; 1.1439x over previous
#include <cuda_runtime.h>
#include <cuda_bf16.h>
#include <cstdint>

#define B_  8
#define C_  64
#define H_  128
#define W_  128
#define OC_ 128
#define HP_ 130
#define WP_ 130

#define ROWB 16640               // one padded row slab: 130 px * 64 ch * 2 B
#define TAPB 16384               // one tap of W
#define STAGE2 32768             // 2 taps per stage
#define SE_OFF   (2 * STAGE2)                // 65536
#define CONV_SMEM (SE_OFF + 3 * ROWB)        // 115456  -> 2 CTAs/SM fits
// rz lives in the dead W stage-0 region after the MMA loop.

// E transposed: [b][hp][wp][c] bf16, border ring = 1.0 (= exp(0))
__device__ __nv_bfloat16 g_Egt[(size_t)B_ * HP_ * WP_ * C_];  // ~17.3 MB
__device__ float         g_Cs[(size_t)B_ * HP_ * WP_];        // channel sums, ring = 64
__device__ __nv_bfloat16 g_Wr[9 * OC_ * C_];                  // [tap][oc][c]

// ---------------------------------------------------------------------------
__device__ __forceinline__ uint32_t smem_u32(const void* p) {
    uint32_t a;
    asm("{ .reg .u64 t; cvta.to.shared.u64 t, %1; cvt.u32.u64 %0, t; }" : "=r"(a) : "l"(p));
    return a;
}
#define CP_ASYNC16(sa, ga) \
    asm volatile("cp.async.cg.shared.global [%0], [%1], 16;" :: "r"(sa), "l"(ga) : "memory")
#define CP_COMMIT() asm volatile("cp.async.commit_group;" ::: "memory")
#define CP_WAIT(n)  asm volatile("cp.async.wait_group %0;" :: "n"(n) : "memory")
#define LDSM_X4(r0, r1, r2, r3, addr) \
    asm volatile("ldmatrix.sync.aligned.m8n8.x4.shared.b16 {%0,%1,%2,%3}, [%4];" \
        : "=r"(r0), "=r"(r1), "=r"(r2), "=r"(r3) : "r"(addr))

__device__ __forceinline__ void mma16816(float* c, const uint32_t* a,
                                         uint32_t b0, uint32_t b1) {
    asm volatile(
        "mma.sync.aligned.m16n8k16.row.col.f32.bf16.bf16.f32 "
        "{%0,%1,%2,%3}, {%4,%5,%6,%7}, {%8,%9}, {%0,%1,%2,%3};"
        : "+f"(c[0]), "+f"(c[1]), "+f"(c[2]), "+f"(c[3])
        : "r"(a[0]), "r"(a[1]), "r"(a[2]), "r"(a[3]), "r"(b0), "r"(b1));
}

// ---------------------------------------------------------------------------
// Fused pre-kernel: blocks [0,2048): exp+transpose+chansum
//                   blocks [2048,..): weight rearrange + border ring
// ---------------------------------------------------------------------------
#define EXP_BLOCKS 2048
#define PREP_TOTAL (9 * OC_ * C_ + B_ * 516)
#define PRE_GRID   (EXP_BLOCKS + (PREP_TOTAL + 255) / 256)

__global__ __launch_bounds__(256) void pre_kernel(const float* __restrict__ x,
                                                  const float* __restrict__ mem) {
    const int bid = blockIdx.x;
    const int tid = threadIdx.x;

    if (bid >= EXP_BLOCKS) {
        int idx = (bid - EXP_BLOCKS) * 256 + tid;
        if (idx < 9 * OC_ * C_) {
            int c   = idx & 63;
            int oc  = (idx >> 6) & 127;
            int tap = idx >> 13;
            g_Wr[idx] = __float2bfloat16(mem[(c * 9 + tap) * OC_ + oc]);
            return;
        }
        idx -= 9 * OC_ * C_;
        if (idx >= B_ * 516) return;
        int b = idx / 516, p = idx % 516;
        int hp, wp;
        if (p < 260) { hp = (p < 130) ? 0 : (HP_ - 1); wp = p % 130; }
        else { int q = p - 260; hp = 1 + (q & 127); wp = (q < 128) ? 0 : (WP_ - 1); }
        size_t pix = ((size_t)b * HP_ + hp) * WP_ + wp;
        uint4 ones = make_uint4(0x3F803F80u, 0x3F803F80u, 0x3F803F80u, 0x3F803F80u);
        uint4* dst = reinterpret_cast<uint4*>(g_Egt + pix * C_);
#pragma unroll
        for (int i = 0; i < 8; i++) dst[i] = ones;
        g_Cs[pix] = 64.0f;
        return;
    }

    __shared__ float sm[C_][65];
    const int w0 = (bid & 1) * 64;
    const int h  = (bid >> 1) & 127;
    const int b  = bid >> 8;
    const int px = tid & 63, cq = tid >> 6;

    const float* xb = x + (((size_t)b * C_) * H_ + h) * W_ + w0 + px;
#pragma unroll
    for (int it = 0; it < 16; it++) {
        int c = it * 4 + cq;
        sm[c][px] = __expf(xb[(size_t)c * H_ * W_]);
    }
    __syncthreads();

    if (tid < 64) {
        float s = 0.f;
#pragma unroll
        for (int c = 0; c < C_; c++) s += sm[c][tid];
        g_Cs[((size_t)b * HP_ + h + 1) * WP_ + (w0 + tid + 1)] = s;
    }

    const int seg = tid & 7, r0 = tid >> 3;
#pragma unroll
    for (int pass = 0; pass < 2; pass++) {
        int r = pass * 32 + r0;
        uint32_t pk[4];
#pragma unroll
        for (int j = 0; j < 4; j++) {
            __nv_bfloat162 v = __floats2bfloat162_rn(sm[seg * 8 + 2 * j][r],
                                                     sm[seg * 8 + 2 * j + 1][r]);
            pk[j] = *reinterpret_cast<uint32_t*>(&v);
        }
        size_t pix = ((size_t)b * HP_ + h + 1) * WP_ + (w0 + r + 1);
        reinterpret_cast<uint4*>(g_Egt + pix * C_)[seg] = make_uint4(pk[0], pk[1], pk[2], pk[3]);
    }
}

// ---------------------------------------------------------------------------
// Conv: per (b,h): D[128 oc, 128 px] = sum_{9 taps} Wtap[128,64] @ Etap[128,64]^T
// E rows h..h+2 resident; W 2-tap double-buffered -> 5 barriers in the loop.
// 8 warps (2M x 4N), 2 CTAs/SM (smem 115456 B).
// ---------------------------------------------------------------------------
__global__ void __launch_bounds__(256, 2) conv_mma_kernel(float* __restrict__ out) {
    extern __shared__ __align__(128) char smem[];
    const uint32_t sbase = smem_u32(smem);
    const int tid  = threadIdx.x;
    const int wid  = tid >> 5, lane = tid & 31;
    const int h = blockIdx.x, b = blockIdx.y;
    const int wm = wid & 1, wn = wid >> 1;    // 2 x 4 warp grid

    const char* EgB = reinterpret_cast<const char*>(g_Egt) + (size_t)b * HP_ * WP_ * C_ * 2;

    auto issueW = [&](int t, uint32_t dst) {   // one 16KB tap
        const uint4* srcA = reinterpret_cast<const uint4*>(g_Wr + t * OC_ * C_);
#pragma unroll
        for (int p = 0; p < 4; p++) {
            int c = p * 256 + tid;
            int off  = c * 16;
            int soff = off ^ ((off >> 3) & 0x70);
            CP_ASYNC16(dst + soff, srcA + c);
        }
    };

    // ---- prologue: E rows h..h+2 (contiguous 49920B) + stage0 = taps {0,1} ----
    {
        const char* srcE = EgB + (size_t)h * ROWB;
        for (int i = tid; i < 3120; i += 256) {
            int slab = i / 1040;
            int r    = i - slab * 1040;
            int off  = r * 16;
            int soff = off ^ ((off >> 3) & 0x70);
            CP_ASYNC16(sbase + SE_OFF + slab * ROWB + soff, srcE + (size_t)i * 16);
        }
    }
    issueW(0, sbase);
    issueW(1, sbase + TAPB);
    CP_COMMIT();

    float acc[4][4][4];
#pragma unroll
    for (int i = 0; i < 4; i++)
#pragma unroll
        for (int j = 0; j < 4; j++)
#pragma unroll
            for (int k = 0; k < 4; k++) acc[i][j][k] = 0.f;

    int aRow[4], aSw[4];
#pragma unroll
    for (int mi = 0; mi < 4; mi++) {
        int row = wm * 64 + mi * 16 + (lane & 15);
        aRow[mi] = row * 128;
        aSw[mi]  = (row & 7) * 16;
    }
    const int aCol = (lane >> 4) << 4;
    int bRowBase[2];
#pragma unroll
    for (int nb = 0; nb < 2; nb++)
        bRowBase[nb] = wn * 32 + nb * 16 + ((lane >> 4) << 3) + (lane & 7);
    const int bCol = ((lane >> 3) & 1) << 4;

#pragma unroll 1
    for (int it = 0; it < 5; it++) {
        CP_WAIT(0);
        __syncthreads();
        {
            int tn = 2 * it + 2;
            if (tn < 9) {
                uint32_t dst = sbase + ((it + 1) & 1) * STAGE2;
                issueW(tn, dst);
                if (tn + 1 < 9) issueW(tn + 1, dst + TAPB);
                CP_COMMIT();
            }
        }

        const uint32_t stg = sbase + (it & 1) * STAGE2;
        const int tcount = (it < 4) ? 2 : 1;
#pragma unroll
        for (int u = 0; u < 2; u++) {
            if (u >= tcount) break;
            const int t  = 2 * it + u;
            const int kh = t / 3, kw = t - 3 * kh;
            const uint32_t sA = stg + u * TAPB;
            const uint32_t sE = sbase + SE_OFF + kh * ROWB;

#pragma unroll
            for (int ks = 0; ks < 4; ks++) {
                uint32_t a[4][4];
#pragma unroll
                for (int mi = 0; mi < 4; mi++) {
                    uint32_t addr = sA + aRow[mi] + ((ks * 32 + aCol) ^ aSw[mi]);
                    LDSM_X4(a[mi][0], a[mi][1], a[mi][2], a[mi][3], addr);
                }
                uint32_t bf[2][4];
#pragma unroll
                for (int nb = 0; nb < 2; nb++) {
                    int row = bRowBase[nb] + kw;
                    uint32_t addr = sE + row * 128 + ((ks * 32 + bCol) ^ ((row & 7) * 16));
                    LDSM_X4(bf[nb][0], bf[nb][1], bf[nb][2], bf[nb][3], addr);
                }
#pragma unroll
                for (int mi = 0; mi < 4; mi++)
#pragma unroll
                    for (int ni = 0; ni < 4; ni++) {
                        uint32_t b0 = bf[ni >> 1][(ni & 1) * 2];
                        uint32_t b1 = bf[ni >> 1][(ni & 1) * 2 + 1];
                        mma16816(acc[mi][ni], a[mi], b0, b1);
                    }
            }
        }
    }
    __syncthreads();

    // ---- softmax denominator into the dead W stage-0 region ----
    float* rz = reinterpret_cast<float*>(smem);   // stage 0 is dead now
    if (tid < 128) {
        const float* Cb = g_Cs + ((size_t)b * HP_ + h) * WP_ + tid;
        float s = 0.f;
#pragma unroll
        for (int i = 0; i < 3; i++)
#pragma unroll
            for (int j = 0; j < 3; j++) s += Cb[i * WP_ + j];
        rz[tid] = 1.0f / s;
    }
    __syncthreads();

    // ---- epilogue: scale + store ----
#pragma unroll
    for (int mi = 0; mi < 4; mi++)
#pragma unroll
        for (int ni = 0; ni < 4; ni++) {
            int oc = wm * 64 + mi * 16 + (lane >> 2);
            int w  = wn * 32 + ni * 8 + (lane & 3) * 2;
            float z0 = rz[w], z1 = rz[w + 1];
            float* p0 = out + (((size_t)b * OC_ + oc) * H_ + h) * W_ + w;
            float2 v0 = make_float2(acc[mi][ni][0] * z0, acc[mi][ni][1] * z1);
            float2 v1 = make_float2(acc[mi][ni][2] * z0, acc[mi][ni][3] * z1);
            *reinterpret_cast<float2*>(p0) = v0;
            *reinterpret_cast<float2*>(p0 + (size_t)8 * H_ * W_) = v1;
        }
}

// ---------------------------------------------------------------------------
extern "C" void kernel_launch(void* const* d_in, const int* in_sizes, int n_in,
                              void* d_out, int out_size) {
    const float* x   = (const float*)d_in[0];   // [8,64,128,128]
    const float* mem = (const float*)d_in[1];   // [576,128]
    float* out = (float*)d_out;                 // [8,128,128,128]

    cudaFuncSetAttribute(conv_mma_kernel,
                         cudaFuncAttributeMaxDynamicSharedMemorySize, CONV_SMEM);

    pre_kernel<<<PRE_GRID, 256>>>(x, mem);
    conv_mma_kernel<<<dim3(H_, B_), 256, CONV_SMEM>>>(out);
}

// round 9
// speedup vs baseline: 1.3018x; 1.0992x over previous
#include <cuda_runtime.h>
#include <cuda_bf16.h>
#include <cstdint>

#define B_  8
#define C_  64
#define H_  128
#define W_  128
#define OC_ 128
#define HP_ 130
#define WP_ 130

#define NSM 152
#define ROWB 16640                   // one padded row slab: 130 px * 64 ch * 2 B
#define TAPB 16384                   // one tap of W
#define SE_OFF (9 * TAPB)            // 147456: E ring (4 slabs)
#define RZ_OFF (SE_OFF + 4 * ROWB)   // 214016: rz ping-pong (2 x 128 floats)
#define CONV_SMEM (RZ_OFF + 1024)    // 215040 <= 227KB max

// E transposed: [b][hp][wp][c] bf16, border ring = 1.0 (= exp(0))
__device__ __nv_bfloat16 g_Egt[(size_t)B_ * HP_ * WP_ * C_];  // ~17.3 MB
__device__ float         g_Cs[(size_t)B_ * HP_ * WP_];        // channel sums, ring = 64
__device__ __nv_bfloat16 g_Wr[9 * OC_ * C_];                  // [tap][oc][c]

// ---------------------------------------------------------------------------
__device__ __forceinline__ uint32_t smem_u32(const void* p) {
    uint32_t a;
    asm("{ .reg .u64 t; cvta.to.shared.u64 t, %1; cvt.u32.u64 %0, t; }" : "=r"(a) : "l"(p));
    return a;
}
#define CP_ASYNC16(sa, ga) \
    asm volatile("cp.async.cg.shared.global [%0], [%1], 16;" :: "r"(sa), "l"(ga) : "memory")
#define CP_COMMIT() asm volatile("cp.async.commit_group;" ::: "memory")
#define CP_WAIT(n)  asm volatile("cp.async.wait_group %0;" :: "n"(n) : "memory")
#define LDSM_X4(r0, r1, r2, r3, addr) \
    asm volatile("ldmatrix.sync.aligned.m8n8.x4.shared.b16 {%0,%1,%2,%3}, [%4];" \
        : "=r"(r0), "=r"(r1), "=r"(r2), "=r"(r3) : "r"(addr))

__device__ __forceinline__ void mma16816(float* c, const uint32_t* a,
                                         uint32_t b0, uint32_t b1) {
    asm volatile(
        "mma.sync.aligned.m16n8k16.row.col.f32.bf16.bf16.f32 "
        "{%0,%1,%2,%3}, {%4,%5,%6,%7}, {%8,%9}, {%0,%1,%2,%3};"
        : "+f"(c[0]), "+f"(c[1]), "+f"(c[2]), "+f"(c[3])
        : "r"(a[0]), "r"(a[1]), "r"(a[2]), "r"(a[3]), "r"(b0), "r"(b1));
}

// ---------------------------------------------------------------------------
// Fused pre-kernel: blocks [0,2048): exp+transpose+chansum
//                   blocks [2048,..): weight rearrange + border ring
// ---------------------------------------------------------------------------
#define EXP_BLOCKS 2048
#define PREP_TOTAL (9 * OC_ * C_ + B_ * 516)
#define PRE_GRID   (EXP_BLOCKS + (PREP_TOTAL + 255) / 256)

__global__ __launch_bounds__(256) void pre_kernel(const float* __restrict__ x,
                                                  const float* __restrict__ mem) {
    const int bid = blockIdx.x;
    const int tid = threadIdx.x;

    if (bid >= EXP_BLOCKS) {
        int idx = (bid - EXP_BLOCKS) * 256 + tid;
        if (idx < 9 * OC_ * C_) {
            int c   = idx & 63;
            int oc  = (idx >> 6) & 127;
            int tap = idx >> 13;
            g_Wr[idx] = __float2bfloat16(mem[(c * 9 + tap) * OC_ + oc]);
            return;
        }
        idx -= 9 * OC_ * C_;
        if (idx >= B_ * 516) return;
        int b = idx / 516, p = idx % 516;
        int hp, wp;
        if (p < 260) { hp = (p < 130) ? 0 : (HP_ - 1); wp = p % 130; }
        else { int q = p - 260; hp = 1 + (q & 127); wp = (q < 128) ? 0 : (WP_ - 1); }
        size_t pix = ((size_t)b * HP_ + hp) * WP_ + wp;
        uint4 ones = make_uint4(0x3F803F80u, 0x3F803F80u, 0x3F803F80u, 0x3F803F80u);
        uint4* dst = reinterpret_cast<uint4*>(g_Egt + pix * C_);
#pragma unroll
        for (int i = 0; i < 8; i++) dst[i] = ones;
        g_Cs[pix] = 64.0f;
        return;
    }

    __shared__ float sm[C_][65];
    const int w0 = (bid & 1) * 64;
    const int h  = (bid >> 1) & 127;
    const int b  = bid >> 8;
    const int px = tid & 63, cq = tid >> 6;

    const float* xb = x + (((size_t)b * C_) * H_ + h) * W_ + w0 + px;
#pragma unroll
    for (int it = 0; it < 16; it++) {
        int c = it * 4 + cq;
        sm[c][px] = __expf(xb[(size_t)c * H_ * W_]);
    }
    __syncthreads();

    if (tid < 64) {
        float s = 0.f;
#pragma unroll
        for (int c = 0; c < C_; c++) s += sm[c][tid];
        g_Cs[((size_t)b * HP_ + h + 1) * WP_ + (w0 + tid + 1)] = s;
    }

    const int seg = tid & 7, r0 = tid >> 3;
#pragma unroll
    for (int pass = 0; pass < 2; pass++) {
        int r = pass * 32 + r0;
        uint32_t pk[4];
#pragma unroll
        for (int j = 0; j < 4; j++) {
            __nv_bfloat162 v = __floats2bfloat162_rn(sm[seg * 8 + 2 * j][r],
                                                     sm[seg * 8 + 2 * j + 1][r]);
            pk[j] = *reinterpret_cast<uint32_t*>(&v);
        }
        size_t pix = ((size_t)b * HP_ + h + 1) * WP_ + (w0 + r + 1);
        reinterpret_cast<uint4*>(g_Egt + pix * C_)[seg] = make_uint4(pk[0], pk[1], pk[2], pk[3]);
    }
}

// ---------------------------------------------------------------------------
// Persistent-strip conv: grid 152 CTAs, each owns ~7 output rows.
// All 9 W taps SM-resident (144KB). E slabs stream through a 4-slot ring,
// 1 new slab + 1 barrier per row. 8 warps (2M x 4N), warp tile 64x32.
// ---------------------------------------------------------------------------
__global__ void __launch_bounds__(256) conv_mma_kernel(float* __restrict__ out) {
    extern __shared__ __align__(128) char smem[];
    const uint32_t sbase = smem_u32(smem);
    const int tid  = threadIdx.x;
    const int wid  = tid >> 5, lane = tid & 31;
    const int wm = wid & 1, wn = wid >> 1;    // 2 x 4 warp grid

    const int r0 = (int)(((long)blockIdx.x * (B_ * H_)) / NSM);
    const int r1 = (int)(((long)(blockIdx.x + 1) * (B_ * H_)) / NSM);

    float* rzbuf = reinterpret_cast<float*>(smem + RZ_OFF);

    // ---- prologue: all 9 W taps (147456 B contiguous) ----
    {
        const char* srcW = reinterpret_cast<const char*>(g_Wr);
        for (int i = tid; i < 9216; i += 256) {
            int off  = i * 16;
            int soff = off ^ ((off >> 3) & 0x70);
            CP_ASYNC16(sbase + soff, srcW + off);
        }
        CP_COMMIT();
    }

    auto issue_slab = [&](const char* EgB, int hp) {
        const char* src = EgB + (size_t)hp * ROWB;
        uint32_t dst = sbase + SE_OFF + (hp & 3) * ROWB;
        for (int i = tid; i < 1040; i += 256) {
            int off  = i * 16;
            int soff = off ^ ((off >> 3) & 0x70);
            CP_ASYNC16(dst + soff, src + off);
        }
    };
    auto write_rz = [&](int row) {
        if (tid < 128) {
            int b = row >> 7, h = row & 127;
            const float* Cb = g_Cs + ((size_t)b * HP_ + h) * WP_ + tid;
            float s = 0.f;
#pragma unroll
            for (int i = 0; i < 3; i++)
#pragma unroll
                for (int j = 0; j < 3; j++) s += Cb[i * WP_ + j];
            rzbuf[(row & 1) * 128 + tid] = 1.0f / s;
        }
    };

    // Per-warp ldmatrix addressing constants
    int aRow[4], aSw[4];
#pragma unroll
    for (int mi = 0; mi < 4; mi++) {
        int row = wm * 64 + mi * 16 + (lane & 15);
        aRow[mi] = row * 128;
        aSw[mi]  = (row & 7) * 16;
    }
    const int aCol = (lane >> 4) << 4;
    int bRowBase[2];
#pragma unroll
    for (int nb = 0; nb < 2; nb++)
        bRowBase[nb] = wn * 32 + nb * 16 + ((lane >> 4) << 3) + (lane & 7);
    const int bCol = ((lane >> 3) & 1) << 4;

    int r = r0;
#pragma unroll 1
    while (r < r1) {
        const int bb = r >> 7;
        const char* EgB = reinterpret_cast<const char*>(g_Egt) +
                          (size_t)bb * HP_ * WP_ * C_ * 2;
        const int seg_end = min(r1, (bb + 1) << 7);

        // segment start: 3 slabs for first row + rz for first row
        {
            int h = r & 127;
            issue_slab(EgB, h);
            issue_slab(EgB, h + 1);
            issue_slab(EgB, h + 2);
            CP_COMMIT();
            write_rz(r);
            CP_WAIT(0);
            __syncthreads();
        }

#pragma unroll 1
        for (int i = r; i < seg_end; i++) {
            const int h = i & 127;
            if (i + 1 < seg_end) { issue_slab(EgB, h + 3); CP_COMMIT(); }
            if (i + 1 < r1) write_rz(i + 1);

            float acc[4][4][4];
#pragma unroll
            for (int a0 = 0; a0 < 4; a0++)
#pragma unroll
                for (int a1 = 0; a1 < 4; a1++)
#pragma unroll
                    for (int a2 = 0; a2 < 4; a2++) acc[a0][a1][a2] = 0.f;

#pragma unroll
            for (int t = 0; t < 9; t++) {
                const int kh = t / 3, kw = t - 3 * kh;
                const uint32_t sA = sbase + t * TAPB;
                const uint32_t sE = sbase + SE_OFF + ((h + kh) & 3) * ROWB;

#pragma unroll
                for (int ks = 0; ks < 4; ks++) {
                    uint32_t a[4][4];
#pragma unroll
                    for (int mi = 0; mi < 4; mi++) {
                        uint32_t addr = sA + aRow[mi] + ((ks * 32 + aCol) ^ aSw[mi]);
                        LDSM_X4(a[mi][0], a[mi][1], a[mi][2], a[mi][3], addr);
                    }
                    uint32_t bf[2][4];
#pragma unroll
                    for (int nb = 0; nb < 2; nb++) {
                        int row = bRowBase[nb] + kw;
                        uint32_t addr = sE + row * 128 +
                                        ((ks * 32 + bCol) ^ ((row & 7) * 16));
                        LDSM_X4(bf[nb][0], bf[nb][1], bf[nb][2], bf[nb][3], addr);
                    }
#pragma unroll
                    for (int mi = 0; mi < 4; mi++)
#pragma unroll
                        for (int ni = 0; ni < 4; ni++) {
                            uint32_t b0 = bf[ni >> 1][(ni & 1) * 2];
                            uint32_t b1 = bf[ni >> 1][(ni & 1) * 2 + 1];
                            mma16816(acc[mi][ni], a[mi], b0, b1);
                        }
                }
            }

            // ---- epilogue: scale + store ----
            const float* rz = rzbuf + (i & 1) * 128;
#pragma unroll
            for (int mi = 0; mi < 4; mi++)
#pragma unroll
                for (int ni = 0; ni < 4; ni++) {
                    int oc = wm * 64 + mi * 16 + (lane >> 2);
                    int w  = wn * 32 + ni * 8 + (lane & 3) * 2;
                    float z0 = rz[w], z1 = rz[w + 1];
                    float* p0 = out + (((size_t)bb * OC_ + oc) * H_ + h) * W_ + w;
                    float2 v0 = make_float2(acc[mi][ni][0] * z0, acc[mi][ni][1] * z1);
                    float2 v1 = make_float2(acc[mi][ni][2] * z0, acc[mi][ni][3] * z1);
                    *reinterpret_cast<float2*>(p0) = v0;
                    *reinterpret_cast<float2*>(p0 + (size_t)8 * H_ * W_) = v1;
                }

            CP_WAIT(0);
            __syncthreads();
        }
        r = seg_end;
    }
}

// ---------------------------------------------------------------------------
extern "C" void kernel_launch(void* const* d_in, const int* in_sizes, int n_in,
                              void* d_out, int out_size) {
    const float* x   = (const float*)d_in[0];   // [8,64,128,128]
    const float* mem = (const float*)d_in[1];   // [576,128]
    float* out = (float*)d_out;                 // [8,128,128,128]

    cudaFuncSetAttribute(conv_mma_kernel,
                         cudaFuncAttributeMaxDynamicSharedMemorySize, CONV_SMEM);

    pre_kernel<<<PRE_GRID, 256>>>(x, mem);
    conv_mma_kernel<<<NSM, 256, CONV_SMEM>>>(out);
}